// round 1
// baseline (speedup 1.0000x reference)
#include <cuda_runtime.h>
#include <cstdint>

#define Bn 2048
#define Dk 1024
#define Mn 16384
#define EPSF 1e-6f

#define BM 128
#define BN 128
#define BK 16
#define TM 8
#define TN 8

// ---------------- device scratch (no allocations allowed) ----------------
__device__ float g_rowconst[Bn];
__device__ float g_colconst[Mn];
__device__ unsigned long long g_best[Bn];

// ---------------- weight column stats: colconst[m] = sum w^2 - 2*eps*sum w ----------------
__global__ void som_wstats(const float* __restrict__ w) {
    int m = blockIdx.x * blockDim.x + threadIdx.x;
    if (m >= Mn) return;
    float s2 = 0.f, s1 = 0.f;
#pragma unroll 8
    for (int d = 0; d < Dk; d++) {
        float v = w[(size_t)d * Mn + m];
        s2 = fmaf(v, v, s2);
        s1 += v;
    }
    g_colconst[m] = s2 - 2.0f * EPSF * s1;
}

// ---------------- x row stats: rowconst[b] = sum x^2 + 2*eps*sum x + D*eps^2 ----------------
__global__ void som_xstats(const float* __restrict__ x) {
    int gwarp = (blockIdx.x * blockDim.x + threadIdx.x) >> 5;
    int lane = threadIdx.x & 31;
    if (gwarp >= Bn) return;
    const float4* xr = (const float4*)(x + (size_t)gwarp * Dk);
    float s2 = 0.f, s1 = 0.f;
#pragma unroll
    for (int i = lane; i < Dk / 4; i += 32) {
        float4 v = xr[i];
        s1 += v.x + v.y + v.z + v.w;
        s2 = fmaf(v.x, v.x, s2);
        s2 = fmaf(v.y, v.y, s2);
        s2 = fmaf(v.z, v.z, s2);
        s2 = fmaf(v.w, v.w, s2);
    }
#pragma unroll
    for (int o = 16; o; o >>= 1) {
        s1 += __shfl_down_sync(0xFFFFFFFFu, s1, o);
        s2 += __shfl_down_sync(0xFFFFFFFFu, s2, o);
    }
    if (lane == 0)
        g_rowconst[gwarp] = s2 + 2.0f * EPSF * s1 + (float)Dk * EPSF * EPSF;
}

// ---------------- init best keys (must happen every launch: graph replays) ----------------
__global__ void som_init_best() {
    int b = blockIdx.x * blockDim.x + threadIdx.x;
    if (b < Bn) g_best[b] = 0xFFFFFFFFFFFFFFFFull;
}

// ---------------- main GEMM + fused min/argmin epilogue ----------------
// grid: (Mn/BN, Bn/BM), block: 256 threads (16x16 micro grid, 8x8 per thread)
__global__ __launch_bounds__(256, 2) void som_gemm(const float* __restrict__ x,
                                                   const float* __restrict__ w) {
    __shared__ union {
        struct {
            float As[BK][BM];  // [k][b]  (x tile, transposed)
            float Bs[BK][BN];  // [k][m]  (w tile)
        } t;
        unsigned long long red[BM][16];
    } sm;

    const int tid = threadIdx.x;
    const int tx = tid & 15;   // N (m) direction
    const int ty = tid >> 4;   // M (b) direction
    const int bRow = blockIdx.y * BM;  // b base
    const int bCol = blockIdx.x * BN;  // m base

    float acc[TM][TN];
#pragma unroll
    for (int i = 0; i < TM; i++)
#pragma unroll
        for (int j = 0; j < TN; j++) acc[i][j] = 0.f;

    // A tile: 128 rows x 16 k  -> 512 float4, 2 per thread
    // thread loads float4 #tid and #(tid+256); f -> row = f>>2, kcol4 = (f&3)
    const int fa0 = tid, fa1 = tid + 256;
    // B tile: 16 k-rows x 128 m -> 512 float4, 2 per thread; f -> krow = f>>5, mcol4 = f&31
    const int fb0 = tid, fb1 = tid + 256;

    const float* Abase0 = x + (size_t)(bRow + (fa0 >> 2)) * Dk + ((fa0 & 3) << 2);
    const float* Abase1 = x + (size_t)(bRow + (fa1 >> 2)) * Dk + ((fa1 & 3) << 2);
    const float* Bbase0 = w + (size_t)(fb0 >> 5) * Mn + bCol + ((fb0 & 31) << 2);
    const float* Bbase1 = w + (size_t)(fb1 >> 5) * Mn + bCol + ((fb1 & 31) << 2);

    float4 pa0 = *(const float4*)(Abase0);
    float4 pa1 = *(const float4*)(Abase1);
    float4 pb0 = *(const float4*)(Bbase0);
    float4 pb1 = *(const float4*)(Bbase1);

    auto store_tiles = [&](float4 a0, float4 a1, float4 b0, float4 b1) {
        int r0 = fa0 >> 2, c0 = (fa0 & 3) << 2;
        sm.t.As[c0 + 0][r0] = a0.x; sm.t.As[c0 + 1][r0] = a0.y;
        sm.t.As[c0 + 2][r0] = a0.z; sm.t.As[c0 + 3][r0] = a0.w;
        int r1 = fa1 >> 2, c1 = (fa1 & 3) << 2;
        sm.t.As[c1 + 0][r1] = a1.x; sm.t.As[c1 + 1][r1] = a1.y;
        sm.t.As[c1 + 2][r1] = a1.z; sm.t.As[c1 + 3][r1] = a1.w;
        *(float4*)&sm.t.Bs[fb0 >> 5][(fb0 & 31) << 2] = b0;
        *(float4*)&sm.t.Bs[fb1 >> 5][(fb1 & 31) << 2] = b1;
    };

    auto compute_tile = [&]() {
#pragma unroll
        for (int kk = 0; kk < BK; kk++) {
            float a[TM], b[TN];
            *(float4*)&a[0] = *(float4*)&sm.t.As[kk][ty * TM];
            *(float4*)&a[4] = *(float4*)&sm.t.As[kk][ty * TM + 4];
            // split columns: low half tx*4, high half 64+tx*4 (conflict-free LDS.128)
            *(float4*)&b[0] = *(float4*)&sm.t.Bs[kk][tx * 4];
            *(float4*)&b[4] = *(float4*)&sm.t.Bs[kk][64 + tx * 4];
#pragma unroll
            for (int i = 0; i < TM; i++)
#pragma unroll
                for (int j = 0; j < TN; j++) acc[i][j] = fmaf(a[i], b[j], acc[i][j]);
        }
    };

    store_tiles(pa0, pa1, pb0, pb1);
    __syncthreads();

#pragma unroll 1
    for (int k0 = BK; k0 < Dk; k0 += BK) {
        float4 na0 = *(const float4*)(Abase0 + k0);
        float4 na1 = *(const float4*)(Abase1 + k0);
        float4 nb0 = *(const float4*)(Bbase0 + (size_t)k0 * Mn);
        float4 nb1 = *(const float4*)(Bbase1 + (size_t)k0 * Mn);
        compute_tile();
        __syncthreads();
        store_tiles(na0, na1, nb0, nb1);
        __syncthreads();
    }
    compute_tile();

    // -------- fused epilogue: sq = rowconst + colconst - 2*dot; min/argmin per row --------
    // column indices for this thread
    int mcol[TN];
#pragma unroll
    for (int j = 0; j < 4; j++) mcol[j] = bCol + tx * 4 + j;
#pragma unroll
    for (int j = 4; j < 8; j++) mcol[j] = bCol + 64 + tx * 4 + (j - 4);

    float cc[TN];
#pragma unroll
    for (int j = 0; j < TN; j++) cc[j] = g_colconst[mcol[j]];

    unsigned long long kbest[TM];
#pragma unroll
    for (int i = 0; i < TM; i++) {
        float rc = g_rowconst[bRow + ty * TM + i];
        unsigned long long kb = 0xFFFFFFFFFFFFFFFFull;
#pragma unroll
        for (int j = 0; j < TN; j++) {
            float sq = fmaxf(rc + cc[j] - 2.0f * acc[i][j], 0.0f);
            unsigned long long key =
                ((unsigned long long)__float_as_uint(sq) << 32) | (unsigned int)mcol[j];
            kb = (key < kb) ? key : kb;
        }
        kbest[i] = kb;
    }

    __syncthreads();  // done with float tiles; reuse smem as u64 reduction buffer
#pragma unroll
    for (int i = 0; i < TM; i++) sm.red[ty * TM + i][tx] = kbest[i];
    __syncthreads();

    if (tid < BM) {
        unsigned long long v = sm.red[tid][0];
#pragma unroll
        for (int t = 1; t < 16; t++) {
            unsigned long long u = sm.red[tid][t];
            v = (u < v) ? u : v;
        }
        atomicMin(&g_best[bRow + tid], v);
    }
}

// ---------------- finalize: write indexes, locations, loss ----------------
__global__ void som_finalize(const float* __restrict__ loc, float* __restrict__ out) {
    __shared__ float ssum[256];
    int tid = threadIdx.x;
    float local = 0.f;
    for (int b = tid; b < Bn; b += 256) {
        unsigned long long v = g_best[b];
        unsigned int m = (unsigned int)(v & 0xFFFFFFFFu);
        float sq = __uint_as_float((unsigned int)(v >> 32));
        float dist = sqrtf(sq);
        out[b] = (float)m;                       // bmu_indexes
        out[Bn + 2 * b + 0] = loc[2 * m + 0];    // bmu_locations x
        out[Bn + 2 * b + 1] = loc[2 * m + 1];    // bmu_locations y
        local += dist;
    }
    ssum[tid] = local;
    __syncthreads();
    for (int s = 128; s; s >>= 1) {
        if (tid < s) ssum[tid] += ssum[tid + s];
        __syncthreads();
    }
    if (tid == 0) out[3 * Bn] = ssum[0] / (float)Bn;  // loss
}

// ---------------- launch ----------------
extern "C" void kernel_launch(void* const* d_in, const int* in_sizes, int n_in,
                              void* d_out, int out_size) {
    const float* x = (const float*)d_in[0];       // [B, D]
    const float* w = (const float*)d_in[1];       // [D, M]
    const float* loc = (const float*)d_in[2];     // [M, 2]
    float* out = (float*)d_out;

    som_wstats<<<(Mn + 255) / 256, 256>>>(w);
    som_xstats<<<(Bn * 32 + 255) / 256, 256>>>(x);
    som_init_best<<<(Bn + 255) / 256, 256>>>();

    dim3 grid(Mn / BN, Bn / BM);
    som_gemm<<<grid, 256>>>(x, w);

    som_finalize<<<1, 256>>>(loc, out);
}

// round 4
// speedup vs baseline: 1.7408x; 1.7408x over previous
#include <cuda_runtime.h>
#include <cuda_bf16.h>
#include <cstdint>

#define Bn 2048
#define Dk 1024
#define Mn 16384
#define EPSF 1e-6f

#define BM 128
#define BN 128
#define BK 16
#define NCHUNKS (Dk / BK)   // 64

// padded smem rows: A row = 16 bf16 = 32B -> 48B; B row = 128 bf16 = 256B -> 272B
#define A_PITCH 48
#define B_PITCH 272

struct __align__(16) Stage {
    uint8_t a_hi[128 * A_PITCH];   // 6144
    uint8_t a_lo[128 * A_PITCH];   // 6144
    uint8_t b_hi[16 * B_PITCH];    // 4352
    uint8_t b_lo[16 * B_PITCH];    // 4352
};

// ---------------- device scratch ----------------
__device__ float g_rowconst[Bn];
__device__ float g_colconst[Mn];
__device__ unsigned long long g_best[Bn];

// ---------------- helpers ----------------
__device__ __forceinline__ uint32_t smem_u32(const void* p) {
    uint32_t a;
    asm("{ .reg .u64 t; cvta.to.shared.u64 t, %1; cvt.u32.u64 %0, t; }" : "=r"(a) : "l"(p));
    return a;
}

__device__ __forceinline__ void ldsm_x4(uint32_t* r, uint32_t addr) {
    asm volatile("ldmatrix.sync.aligned.m8n8.x4.shared.b16 {%0,%1,%2,%3}, [%4];"
                 : "=r"(r[0]), "=r"(r[1]), "=r"(r[2]), "=r"(r[3]) : "r"(addr));
}
__device__ __forceinline__ void ldsm_x4_t(uint32_t* r, uint32_t addr) {
    asm volatile("ldmatrix.sync.aligned.m8n8.x4.trans.shared.b16 {%0,%1,%2,%3}, [%4];"
                 : "=r"(r[0]), "=r"(r[1]), "=r"(r[2]), "=r"(r[3]) : "r"(addr));
}
__device__ __forceinline__ void mma_bf16(float* c, const uint32_t* a, const uint32_t* b) {
    asm volatile(
        "mma.sync.aligned.m16n8k16.row.col.f32.bf16.bf16.f32 "
        "{%0,%1,%2,%3}, {%4,%5,%6,%7}, {%8,%9}, {%0,%1,%2,%3};"
        : "+f"(c[0]), "+f"(c[1]), "+f"(c[2]), "+f"(c[3])
        : "r"(a[0]), "r"(a[1]), "r"(a[2]), "r"(a[3]), "r"(b[0]), "r"(b[1]));
}

// split a pair of floats into packed bf16 hi and packed bf16 residual lo
__device__ __forceinline__ void hilo2(float a, float b, uint32_t& h, uint32_t& l) {
    asm("cvt.rn.bf16x2.f32 %0, %1, %2;" : "=r"(h) : "f"(b), "f"(a));  // {lo16=a, hi16=b}
    float ha = __uint_as_float(h << 16);
    float hb = __uint_as_float(h & 0xFFFF0000u);
    float ra = a - ha, rb = b - hb;
    asm("cvt.rn.bf16x2.f32 %0, %1, %2;" : "=r"(l) : "f"(rb), "f"(ra));
}

// ---------------- stats / init / finalize ----------------
__global__ void som_wstats(const float* __restrict__ w) {
    int m = blockIdx.x * blockDim.x + threadIdx.x;
    if (m >= Mn) return;
    float s2 = 0.f, s1 = 0.f;
#pragma unroll 8
    for (int d = 0; d < Dk; d++) {
        float v = w[(size_t)d * Mn + m];
        s2 = fmaf(v, v, s2);
        s1 += v;
    }
    g_colconst[m] = s2 - 2.0f * EPSF * s1;
}

__global__ void som_xstats(const float* __restrict__ x) {
    int gw = (blockIdx.x * blockDim.x + threadIdx.x) >> 5;
    int lane = threadIdx.x & 31;
    if (gw >= Bn) return;
    const float4* xr = (const float4*)(x + (size_t)gw * Dk);
    float s2 = 0.f, s1 = 0.f;
#pragma unroll
    for (int i = lane; i < Dk / 4; i += 32) {
        float4 v = xr[i];
        s1 += v.x + v.y + v.z + v.w;
        s2 = fmaf(v.x, v.x, s2); s2 = fmaf(v.y, v.y, s2);
        s2 = fmaf(v.z, v.z, s2); s2 = fmaf(v.w, v.w, s2);
    }
#pragma unroll
    for (int o = 16; o; o >>= 1) {
        s1 += __shfl_down_sync(0xFFFFFFFFu, s1, o);
        s2 += __shfl_down_sync(0xFFFFFFFFu, s2, o);
    }
    if (lane == 0) g_rowconst[gw] = s2 + 2.0f * EPSF * s1 + (float)Dk * EPSF * EPSF;
}

__global__ void som_init_best() {
    int b = blockIdx.x * blockDim.x + threadIdx.x;
    if (b < Bn) g_best[b] = 0xFFFFFFFFFFFFFFFFull;
}

__global__ void som_finalize(const float* __restrict__ loc, float* __restrict__ out) {
    __shared__ float ssum[256];
    int tid = threadIdx.x;
    float local = 0.f;
    for (int b = tid; b < Bn; b += 256) {
        unsigned long long v = g_best[b];
        unsigned int m = (unsigned int)(v & 0xFFFFFFFFu);
        float sq = __uint_as_float((unsigned int)(v >> 32));
        out[b] = (float)m;
        out[Bn + 2 * b + 0] = loc[2 * m + 0];
        out[Bn + 2 * b + 1] = loc[2 * m + 1];
        local += sqrtf(sq);
    }
    ssum[tid] = local;
    __syncthreads();
    for (int s = 128; s; s >>= 1) {
        if (tid < s) ssum[tid] += ssum[tid + s];
        __syncthreads();
    }
    if (tid == 0) out[3 * Bn] = ssum[0] / (float)Bn;
}

// ---------------- main mma.sync kernel ----------------
__global__ __launch_bounds__(256, 1) void som_mma(const float* __restrict__ x,
                                                  const float* __restrict__ w) {
    __shared__ Stage stg[2];

    const int tid = threadIdx.x;
    const int lid = tid & 31;
    const int wid = tid >> 5;
    const int warp_m = wid >> 2;   // 0..1 -> rows warp_m*64
    const int warp_n = wid & 3;    // 0..3 -> cols warp_n*32
    const int bRow = blockIdx.x * BM;
    const int bCol = blockIdx.y * BN;

    float acc[4][4][4];
#pragma unroll
    for (int i = 0; i < 4; i++)
#pragma unroll
        for (int j = 0; j < 4; j++)
#pragma unroll
            for (int k = 0; k < 4; k++) acc[i][j][k] = 0.f;

    // --- gmem prefetch pointers (per thread) ---
    // A: thread t -> row t>>1, k-chunk half t&1 (8 floats)
    const float* aptr = x + (size_t)(bRow + (tid >> 1)) * Dk + (tid & 1) * 8;
    // B: thread t -> k-row t>>4, n-chunk t&15 (8 floats)
    const float* bptr = w + (size_t)(tid >> 4) * Mn + bCol + (tid & 15) * 8;

    // smem store offsets for conversion
    const uint32_t a_st = (tid >> 1) * A_PITCH + (tid & 1) * 16;
    const uint32_t b_st = (tid >> 4) * B_PITCH + (tid & 15) * 16;

    // ldmatrix lane addresses
    // A (non-trans x4): lanes 0-15 -> rows 0-15 chunk0 (k0-7), lanes 16-31 -> chunk1 (k8-15)
    const uint32_t a_ld = (warp_m * 64 + (lid & 15)) * A_PITCH + (lid >> 4) * 16;
    // B (trans x4): mat = lid>>3; krow = (mat&1)*8 + (lid&7); noff = (mat>>1)*16 bytes
    const uint32_t b_ld = (((lid >> 3) & 1) * 8 + (lid & 7)) * B_PITCH +
                          warp_n * 64 + ((lid >> 3) >> 1) * 16;

    uint32_t sbase[2] = {smem_u32(&stg[0]), smem_u32(&stg[1])};
    const uint32_t off_alo = (uint32_t)(offsetof(Stage, a_lo));
    const uint32_t off_bhi = (uint32_t)(offsetof(Stage, b_hi));
    const uint32_t off_blo = (uint32_t)(offsetof(Stage, b_lo));

    float4 pa0, pa1, pb0, pb1;
    pa0 = *(const float4*)(aptr);
    pa1 = *(const float4*)(aptr + 4);
    pb0 = *(const float4*)(bptr);
    pb1 = *(const float4*)(bptr + 4);

#pragma unroll 1
    for (int c = 0; c < NCHUNKS; c++) {
        const uint32_t sb = sbase[c & 1];
        // ---- convert & store (A: 8 floats, B: 8 floats per thread) ----
        {
            uint32_t h0, h1, h2, h3, l0, l1, l2, l3;
            hilo2(pa0.x, pa0.y, h0, l0); hilo2(pa0.z, pa0.w, h1, l1);
            hilo2(pa1.x, pa1.y, h2, l2); hilo2(pa1.z, pa1.w, h3, l3);
            *(uint4*)(stg[c & 1].a_hi + a_st) = make_uint4(h0, h1, h2, h3);
            *(uint4*)(stg[c & 1].a_lo + a_st) = make_uint4(l0, l1, l2, l3);
            hilo2(pb0.x, pb0.y, h0, l0); hilo2(pb0.z, pb0.w, h1, l1);
            hilo2(pb1.x, pb1.y, h2, l2); hilo2(pb1.z, pb1.w, h3, l3);
            *(uint4*)(stg[c & 1].b_hi + b_st) = make_uint4(h0, h1, h2, h3);
            *(uint4*)(stg[c & 1].b_lo + b_st) = make_uint4(l0, l1, l2, l3);
        }
        __syncthreads();

        // ---- prefetch next chunk (hidden under the MMAs below) ----
        if (c + 1 < NCHUNKS) {
            pa0 = *(const float4*)(aptr + (c + 1) * BK);
            pa1 = *(const float4*)(aptr + (c + 1) * BK + 4);
            pb0 = *(const float4*)(bptr + (size_t)(c + 1) * BK * Mn);
            pb1 = *(const float4*)(bptr + (size_t)(c + 1) * BK * Mn + 4);
        }

        // ---- fragment loads ----
        uint32_t a_hi[4][4], a_lo[4][4], b_hi[2][4], b_lo[2][4];
#pragma unroll
        for (int mt = 0; mt < 4; mt++) {
            ldsm_x4(a_hi[mt], sb + a_ld + mt * 16 * A_PITCH);
            ldsm_x4(a_lo[mt], sb + off_alo + a_ld + mt * 16 * A_PITCH);
        }
#pragma unroll
        for (int g = 0; g < 2; g++) {  // each covers 2 n8-tiles
            ldsm_x4_t(b_hi[g], sb + off_bhi + b_ld + g * 32);
            ldsm_x4_t(b_lo[g], sb + off_blo + b_ld + g * 32);
        }

        // ---- 48 MMAs: hi*hi, hi*lo, lo*hi ----
#pragma unroll
        for (int mt = 0; mt < 4; mt++)
#pragma unroll
            for (int nt = 0; nt < 4; nt++)
                mma_bf16(acc[mt][nt], a_hi[mt], &b_hi[nt >> 1][(nt & 1) * 2]);
#pragma unroll
        for (int mt = 0; mt < 4; mt++)
#pragma unroll
            for (int nt = 0; nt < 4; nt++)
                mma_bf16(acc[mt][nt], a_hi[mt], &b_lo[nt >> 1][(nt & 1) * 2]);
#pragma unroll
        for (int mt = 0; mt < 4; mt++)
#pragma unroll
            for (int nt = 0; nt < 4; nt++)
                mma_bf16(acc[mt][nt], a_lo[mt], &b_hi[nt >> 1][(nt & 1) * 2]);
    }

    // ---- epilogue: sq = rowconst + colconst - 2*dot ; min/argmin ----
    // c-frag mapping: reg r: row = (lid>>2) + (r>>1)*8, col = (lid&3)*2 + (r&1)
    float ccv[4][2];
    const int cbase = bCol + warp_n * 32 + (lid & 3) * 2;
#pragma unroll
    for (int nt = 0; nt < 4; nt++) {
        ccv[nt][0] = __ldg(&g_colconst[cbase + nt * 8]);
        ccv[nt][1] = __ldg(&g_colconst[cbase + nt * 8 + 1]);
    }

#pragma unroll
    for (int mt = 0; mt < 4; mt++) {
#pragma unroll
        for (int half = 0; half < 2; half++) {
            const int row = bRow + warp_m * 64 + mt * 16 + (lid >> 2) + half * 8;
            const float rc = __ldg(&g_rowconst[row]);
            unsigned long long best = 0xFFFFFFFFFFFFFFFFull;
#pragma unroll
            for (int nt = 0; nt < 4; nt++) {
#pragma unroll
                for (int q = 0; q < 2; q++) {
                    float sq = fmaxf(rc + ccv[nt][q] - 2.0f * acc[mt][nt][half * 2 + q], 0.0f);
                    int m = cbase + nt * 8 + q;
                    unsigned long long key =
                        ((unsigned long long)__float_as_uint(sq) << 32) | (unsigned int)m;
                    best = (key < best) ? key : best;
                }
            }
            // quad reduce (lanes sharing this row)
            unsigned long long o1 = __shfl_xor_sync(0xFFFFFFFFu, best, 1);
            best = (o1 < best) ? o1 : best;
            unsigned long long o2 = __shfl_xor_sync(0xFFFFFFFFu, best, 2);
            best = (o2 < best) ? o2 : best;
            if ((lid & 3) == 0) atomicMin(&g_best[row], best);
        }
    }
}

// ---------------- launch ----------------
extern "C" void kernel_launch(void* const* d_in, const int* in_sizes, int n_in,
                              void* d_out, int out_size) {
    const float* x = (const float*)d_in[0];   // [B, D]
    const float* w = (const float*)d_in[1];   // [D, M]
    const float* loc = (const float*)d_in[2]; // [M, 2]
    float* out = (float*)d_out;

    som_wstats<<<(Mn + 255) / 256, 256>>>(w);
    som_xstats<<<(Bn * 32 + 255) / 256, 256>>>(x);
    som_init_best<<<(Bn + 255) / 256, 256>>>();

    dim3 grid(Bn / BM, Mn / BN);   // x fastest = B-tiles: consecutive CTAs share w panel (L2 reuse)
    som_mma<<<grid, 256>>>(x, w);

    som_finalize<<<1, 256>>>(loc, out);
}

// round 5
// speedup vs baseline: 2.3512x; 1.3506x over previous
#include <cuda_runtime.h>
#include <cuda_bf16.h>
#include <cstdint>

#define Bn 2048
#define Dk 1024
#define Mn 16384
#define EPSF 1e-6f

#define BM 128
#define BN 128
#define BK 32
#define NCH (Dk / BK)        // 32 chunks

// padded pitches (bytes): A row = 32 bf16 = 64B -> 80; B row = 128 bf16 = 256B -> 272
#define A_PITCH 80
#define B_PITCH 272
#define A_HI 0
#define A_LO 10240           // 128*80
#define B_HI 20480
#define B_LO 29184           // +32*272
#define STAGE_SZ 37888
#define DYN_BYTES (2 * STAGE_SZ)

#define DSLICE 8             // wstats slices

// ---------------- device scratch ----------------
__device__ float g_rowconst[Bn];
__device__ float g_colconst[Mn];
__device__ float g_colpart[DSLICE * Mn];
__device__ unsigned long long g_best[Bn];
__device__ __nv_bfloat16 g_xhi[Bn * Dk];
__device__ __nv_bfloat16 g_xlo[Bn * Dk];
__device__ __nv_bfloat16 g_whi[(size_t)Dk * Mn];
__device__ __nv_bfloat16 g_wlo[(size_t)Dk * Mn];

// ---------------- helpers ----------------
__device__ __forceinline__ uint32_t smem_u32(const void* p) {
    uint32_t a;
    asm("{ .reg .u64 t; cvta.to.shared.u64 t, %1; cvt.u32.u64 %0, t; }" : "=r"(a) : "l"(p));
    return a;
}
__device__ __forceinline__ void cp16(uint32_t s, const void* g) {
    asm volatile("cp.async.cg.shared.global [%0], [%1], 16;" :: "r"(s), "l"(g) : "memory");
}
__device__ __forceinline__ void cp_commit() { asm volatile("cp.async.commit_group;" ::: "memory"); }
__device__ __forceinline__ void cp_wait1()  { asm volatile("cp.async.wait_group 1;" ::: "memory"); }

__device__ __forceinline__ void ldsm_x4(uint32_t* r, uint32_t addr) {
    asm volatile("ldmatrix.sync.aligned.m8n8.x4.shared.b16 {%0,%1,%2,%3}, [%4];"
                 : "=r"(r[0]), "=r"(r[1]), "=r"(r[2]), "=r"(r[3]) : "r"(addr));
}
__device__ __forceinline__ void ldsm_x4_t(uint32_t* r, uint32_t addr) {
    asm volatile("ldmatrix.sync.aligned.m8n8.x4.trans.shared.b16 {%0,%1,%2,%3}, [%4];"
                 : "=r"(r[0]), "=r"(r[1]), "=r"(r[2]), "=r"(r[3]) : "r"(addr));
}
__device__ __forceinline__ void mma_bf16(float* c, const uint32_t* a, const uint32_t* b) {
    asm volatile(
        "mma.sync.aligned.m16n8k16.row.col.f32.bf16.bf16.f32 "
        "{%0,%1,%2,%3}, {%4,%5,%6,%7}, {%8,%9}, {%0,%1,%2,%3};"
        : "+f"(c[0]), "+f"(c[1]), "+f"(c[2]), "+f"(c[3])
        : "r"(a[0]), "r"(a[1]), "r"(a[2]), "r"(a[3]), "r"(b[0]), "r"(b[1]));
}
__device__ __forceinline__ void hilo1(float a, __nv_bfloat16& h, __nv_bfloat16& l) {
    h = __float2bfloat16(a);
    l = __float2bfloat16(a - __bfloat162float(h));
}

// ---------------- w convert + partial stats ----------------
__global__ void som_wconv(const float* __restrict__ w) {
    int m = blockIdx.x * blockDim.x + threadIdx.x;        // 0..Mn-1
    int z = blockIdx.y;                                    // 0..DSLICE-1
    int d0 = z * (Dk / DSLICE);
    float s2 = 0.f, s1 = 0.f;
#pragma unroll 4
    for (int i = 0; i < Dk / DSLICE; i++) {
        size_t idx = (size_t)(d0 + i) * Mn + m;
        float v = w[idx];
        s2 = fmaf(v, v, s2);
        s1 += v;
        __nv_bfloat16 h, l;
        hilo1(v, h, l);
        g_whi[idx] = h;
        g_wlo[idx] = l;
    }
    g_colpart[z * Mn + m] = s2 - 2.0f * EPSF * s1;
}

__global__ void som_colreduce() {
    int m = blockIdx.x * blockDim.x + threadIdx.x;
    float s = 0.f;
#pragma unroll
    for (int z = 0; z < DSLICE; z++) s += g_colpart[z * Mn + m];
    g_colconst[m] = s;
}

// ---------------- x convert + stats (warp per row) ----------------
__global__ void som_xconv(const float* __restrict__ x) {
    int gw = (blockIdx.x * blockDim.x + threadIdx.x) >> 5;
    int lane = threadIdx.x & 31;
    if (gw >= Bn) return;
    const float4* xr = (const float4*)(x + (size_t)gw * Dk);
    float s2 = 0.f, s1 = 0.f;
#pragma unroll
    for (int i = lane; i < Dk / 4; i += 32) {
        float4 v = xr[i];
        s1 += v.x + v.y + v.z + v.w;
        s2 = fmaf(v.x, v.x, s2); s2 = fmaf(v.y, v.y, s2);
        s2 = fmaf(v.z, v.z, s2); s2 = fmaf(v.w, v.w, s2);
        __nv_bfloat16 h[4], l[4];
        hilo1(v.x, h[0], l[0]); hilo1(v.y, h[1], l[1]);
        hilo1(v.z, h[2], l[2]); hilo1(v.w, h[3], l[3]);
        *(uint2*)&g_xhi[(size_t)gw * Dk + i * 4] = *(uint2*)h;
        *(uint2*)&g_xlo[(size_t)gw * Dk + i * 4] = *(uint2*)l;
    }
#pragma unroll
    for (int o = 16; o; o >>= 1) {
        s1 += __shfl_down_sync(0xFFFFFFFFu, s1, o);
        s2 += __shfl_down_sync(0xFFFFFFFFu, s2, o);
    }
    if (lane == 0) g_rowconst[gw] = s2 + 2.0f * EPSF * s1 + (float)Dk * EPSF * EPSF;
}

__global__ void som_init_best() {
    int b = blockIdx.x * blockDim.x + threadIdx.x;
    if (b < Bn) g_best[b] = 0xFFFFFFFFFFFFFFFFull;
}

__global__ void som_finalize(const float* __restrict__ loc, float* __restrict__ out) {
    __shared__ float ssum[256];
    int tid = threadIdx.x;
    float local = 0.f;
    for (int b = tid; b < Bn; b += 256) {
        unsigned long long v = g_best[b];
        unsigned int m = (unsigned int)(v & 0xFFFFFFFFu);
        float sq = __uint_as_float((unsigned int)(v >> 32));
        out[b] = (float)m;
        out[Bn + 2 * b + 0] = loc[2 * m + 0];
        out[Bn + 2 * b + 1] = loc[2 * m + 1];
        local += sqrtf(sq);
    }
    ssum[tid] = local;
    __syncthreads();
    for (int s = 128; s; s >>= 1) {
        if (tid < s) ssum[tid] += ssum[tid + s];
        __syncthreads();
    }
    if (tid == 0) out[3 * Bn] = ssum[0] / (float)Bn;
}

// ---------------- main GEMM ----------------
__global__ __launch_bounds__(256, 2) void som_mma(void) {
    extern __shared__ uint8_t dyn[];

    const int tid = threadIdx.x;
    const int lid = tid & 31;
    const int wid = tid >> 5;
    const int warp_m = wid >> 2;
    const int warp_n = wid & 3;
    const int bRow = blockIdx.x * BM;
    const int bCol = blockIdx.y * BN;

    float acc[4][4][4];
#pragma unroll
    for (int i = 0; i < 4; i++)
#pragma unroll
        for (int j = 0; j < 4; j++)
#pragma unroll
            for (int k = 0; k < 4; k++) acc[i][j][k] = 0.f;

    const uint32_t sb0 = smem_u32(dyn);

    // cp.async chunk mapping
    // A: 512 x 16B per buffer; q -> row=q>>2, kc=q&3
    const int qa0 = tid, qa1 = tid + 256;
    const uint32_t a_s0 = (qa0 >> 2) * A_PITCH + (qa0 & 3) * 16;
    const uint32_t a_s1 = (qa1 >> 2) * A_PITCH + (qa1 & 3) * 16;
    const size_t a_g0 = (size_t)(bRow + (qa0 >> 2)) * Dk + (qa0 & 3) * 8;
    const size_t a_g1 = (size_t)(bRow + (qa1 >> 2)) * Dk + (qa1 & 3) * 8;
    // B: 512 x 16B per buffer; q -> row=q>>4, nc=q&15
    const int qb0 = tid, qb1 = tid + 256;
    const uint32_t b_s0 = (qb0 >> 4) * B_PITCH + (qb0 & 15) * 16;
    const uint32_t b_s1 = (qb1 >> 4) * B_PITCH + (qb1 & 15) * 16;
    const size_t b_g0 = (size_t)(qb0 >> 4) * Mn + bCol + (qb0 & 15) * 8;
    const size_t b_g1 = (size_t)(qb1 >> 4) * Mn + bCol + (qb1 & 15) * 8;

    auto issue_stage = [&](int c) {
        const uint32_t sb = sb0 + (c & 1) * STAGE_SZ;
        const int k0 = c * BK;
        cp16(sb + A_HI + a_s0, g_xhi + a_g0 + k0);
        cp16(sb + A_HI + a_s1, g_xhi + a_g1 + k0);
        cp16(sb + A_LO + a_s0, g_xlo + a_g0 + k0);
        cp16(sb + A_LO + a_s1, g_xlo + a_g1 + k0);
        cp16(sb + B_HI + b_s0, g_whi + b_g0 + (size_t)k0 * Mn);
        cp16(sb + B_HI + b_s1, g_whi + b_g1 + (size_t)k0 * Mn);
        cp16(sb + B_LO + b_s0, g_wlo + b_g0 + (size_t)k0 * Mn);
        cp16(sb + B_LO + b_s1, g_wlo + b_g1 + (size_t)k0 * Mn);
    };

    // ldmatrix lane addressing
    const uint32_t a_ld = (warp_m * 64 + (lid & 15)) * A_PITCH + (lid >> 4) * 16;
    const uint32_t b_ld = (((lid >> 3) & 1) * 8 + (lid & 7)) * B_PITCH +
                          warp_n * 64 + ((lid >> 3) >> 1) * 16;

    issue_stage(0); cp_commit();
    issue_stage(1); cp_commit();

#pragma unroll 1
    for (int c = 0; c < NCH; c++) {
        cp_wait1();
        __syncthreads();
        const uint32_t sb = sb0 + (c & 1) * STAGE_SZ;

#pragma unroll
        for (int ks = 0; ks < 2; ks++) {
            uint32_t bh[2][4], bl[2][4], af[4][4];
#pragma unroll
            for (int g = 0; g < 2; g++) {
                ldsm_x4_t(bh[g], sb + B_HI + b_ld + ks * 16 * B_PITCH + g * 32);
                ldsm_x4_t(bl[g], sb + B_LO + b_ld + ks * 16 * B_PITCH + g * 32);
            }
#pragma unroll
            for (int mt = 0; mt < 4; mt++)
                ldsm_x4(af[mt], sb + A_HI + a_ld + mt * 16 * A_PITCH + ks * 32);
#pragma unroll
            for (int mt = 0; mt < 4; mt++)
#pragma unroll
                for (int nt = 0; nt < 4; nt++)
                    mma_bf16(acc[mt][nt], af[mt], &bh[nt >> 1][(nt & 1) * 2]);
#pragma unroll
            for (int mt = 0; mt < 4; mt++)
#pragma unroll
                for (int nt = 0; nt < 4; nt++)
                    mma_bf16(acc[mt][nt], af[mt], &bl[nt >> 1][(nt & 1) * 2]);
#pragma unroll
            for (int mt = 0; mt < 4; mt++)
                ldsm_x4(af[mt], sb + A_LO + a_ld + mt * 16 * A_PITCH + ks * 32);
#pragma unroll
            for (int mt = 0; mt < 4; mt++)
#pragma unroll
                for (int nt = 0; nt < 4; nt++)
                    mma_bf16(acc[mt][nt], af[mt], &bh[nt >> 1][(nt & 1) * 2]);
        }

        __syncthreads();
        if (c + 2 < NCH) issue_stage(c + 2);
        cp_commit();
    }

    // ---- epilogue: sq = rowconst + colconst - 2*dot ; min/argmin ----
    float ccv[4][2];
    const int cbase = bCol + warp_n * 32 + (lid & 3) * 2;
#pragma unroll
    for (int nt = 0; nt < 4; nt++) {
        ccv[nt][0] = __ldg(&g_colconst[cbase + nt * 8]);
        ccv[nt][1] = __ldg(&g_colconst[cbase + nt * 8 + 1]);
    }

#pragma unroll
    for (int mt = 0; mt < 4; mt++) {
#pragma unroll
        for (int half = 0; half < 2; half++) {
            const int row = bRow + warp_m * 64 + mt * 16 + (lid >> 2) + half * 8;
            const float rc = __ldg(&g_rowconst[row]);
            unsigned long long best = 0xFFFFFFFFFFFFFFFFull;
#pragma unroll
            for (int nt = 0; nt < 4; nt++) {
#pragma unroll
                for (int q = 0; q < 2; q++) {
                    float sq = fmaxf(rc + ccv[nt][q] - 2.0f * acc[mt][nt][half * 2 + q], 0.0f);
                    int m = cbase + nt * 8 + q;
                    unsigned long long key =
                        ((unsigned long long)__float_as_uint(sq) << 32) | (unsigned int)m;
                    best = (key < best) ? key : best;
                }
            }
            unsigned long long o1 = __shfl_xor_sync(0xFFFFFFFFu, best, 1);
            best = (o1 < best) ? o1 : best;
            unsigned long long o2 = __shfl_xor_sync(0xFFFFFFFFu, best, 2);
            best = (o2 < best) ? o2 : best;
            if ((lid & 3) == 0) atomicMin(&g_best[row], best);
        }
    }
}

// ---------------- launch ----------------
extern "C" void kernel_launch(void* const* d_in, const int* in_sizes, int n_in,
                              void* d_out, int out_size) {
    const float* x = (const float*)d_in[0];   // [B, D]
    const float* w = (const float*)d_in[1];   // [D, M]
    const float* loc = (const float*)d_in[2]; // [M, 2]
    float* out = (float*)d_out;

    static int configured = 0;
    if (!configured) {
        cudaFuncSetAttribute(som_mma, cudaFuncAttributeMaxDynamicSharedMemorySize, DYN_BYTES);
        configured = 1;
    }

    som_wconv<<<dim3(Mn / 256, DSLICE), 256>>>(w);
    som_xconv<<<Bn * 32 / 256, 256>>>(x);
    som_colreduce<<<Mn / 256, 256>>>();
    som_init_best<<<Bn / 256, 256>>>();

    dim3 grid(Bn / BM, Mn / BN);   // x fastest: consecutive CTAs share the w panel (L2 reuse)
    som_mma<<<grid, 256, DYN_BYTES>>>();

    som_finalize<<<1, 256>>>(loc, out);
}

// round 7
// speedup vs baseline: 3.5433x; 1.5070x over previous
#include <cuda_runtime.h>
#include <cuda_bf16.h>
#include <cuda_fp16.h>
#include <cstdint>

#define Bn 2048
#define Dk 1024
#define Mn 16384
#define EPSF 1e-6f

#define BM 128
#define BN 128
#define BK 32
#define NCH (Dk / BK)        // 32 chunks

// padded pitches (bytes): A row = 32 bf16 = 64B -> 80; B row = 128 bf16 = 256B -> 272
#define A_PITCH 80
#define B_PITCH 272
#define A_HI 0
#define B_HI 10240           // 128*80
#define STAGE_SZ 18944       // +32*272
#define DOT_PITCH 136        // halves per row in smem dot tile (272B: 16B-aligned rows)
#define DYN_BYTES 37888      // max(2*STAGE_SZ=37888, 128*DOT_PITCH*2=34816)

#define DSLICE 8
#define E_MARGIN 3.5f
#define CAND_CAP (1 << 20)

// ---------------- device scratch ----------------
__device__ float g_rowconst[Bn];
__device__ float g_colconst[Mn];
__device__ float g_colpart[DSLICE * Mn];
__device__ unsigned long long g_best[Bn];    // approx (pass 1)
__device__ unsigned long long g_best2[Bn];   // exact (pass 3)
__device__ __nv_bfloat16 g_xhi[Bn * Dk];
__device__ __nv_bfloat16 g_whi[(size_t)Dk * Mn];
__device__ __half g_dot[(size_t)Bn * Mn];
__device__ int2 g_cand[CAND_CAP];
__device__ int g_ncand;

// ---------------- helpers ----------------
__device__ __forceinline__ uint32_t smem_u32(const void* p) {
    uint32_t a;
    asm("{ .reg .u64 t; cvta.to.shared.u64 t, %1; cvt.u32.u64 %0, t; }" : "=r"(a) : "l"(p));
    return a;
}
__device__ __forceinline__ void cp16(uint32_t s, const void* g) {
    asm volatile("cp.async.cg.shared.global [%0], [%1], 16;" :: "r"(s), "l"(g) : "memory");
}
__device__ __forceinline__ void cp_commit() { asm volatile("cp.async.commit_group;" ::: "memory"); }
__device__ __forceinline__ void cp_wait1()  { asm volatile("cp.async.wait_group 1;" ::: "memory"); }

__device__ __forceinline__ void ldsm_x4(uint32_t* r, uint32_t addr) {
    asm volatile("ldmatrix.sync.aligned.m8n8.x4.shared.b16 {%0,%1,%2,%3}, [%4];"
                 : "=r"(r[0]), "=r"(r[1]), "=r"(r[2]), "=r"(r[3]) : "r"(addr));
}
__device__ __forceinline__ void ldsm_x4_t(uint32_t* r, uint32_t addr) {
    asm volatile("ldmatrix.sync.aligned.m8n8.x4.trans.shared.b16 {%0,%1,%2,%3}, [%4];"
                 : "=r"(r[0]), "=r"(r[1]), "=r"(r[2]), "=r"(r[3]) : "r"(addr));
}
__device__ __forceinline__ void mma_bf16(float* c, const uint32_t* a, const uint32_t* b) {
    asm volatile(
        "mma.sync.aligned.m16n8k16.row.col.f32.bf16.bf16.f32 "
        "{%0,%1,%2,%3}, {%4,%5,%6,%7}, {%8,%9}, {%0,%1,%2,%3};"
        : "+f"(c[0]), "+f"(c[1]), "+f"(c[2]), "+f"(c[3])
        : "r"(a[0]), "r"(a[1]), "r"(a[2]), "r"(a[3]), "r"(b[0]), "r"(b[1]));
}

// ---------------- w convert + partial stats ----------------
__global__ void som_wconv(const float* __restrict__ w) {
    int m = blockIdx.x * blockDim.x + threadIdx.x;
    int z = blockIdx.y;
    int d0 = z * (Dk / DSLICE);
    float s2 = 0.f, s1 = 0.f;
#pragma unroll 4
    for (int i = 0; i < Dk / DSLICE; i++) {
        size_t idx = (size_t)(d0 + i) * Mn + m;
        float v = w[idx];
        s2 = fmaf(v, v, s2);
        s1 += v;
        g_whi[idx] = __float2bfloat16(v);
    }
    g_colpart[z * Mn + m] = s2 - 2.0f * EPSF * s1;
}

__global__ void som_colreduce() {
    int m = blockIdx.x * blockDim.x + threadIdx.x;
    float s = 0.f;
#pragma unroll
    for (int z = 0; z < DSLICE; z++) s += g_colpart[z * Mn + m];
    g_colconst[m] = s;
}

// ---------------- x convert + stats ----------------
__global__ void som_xconv(const float* __restrict__ x) {
    int gw = (blockIdx.x * blockDim.x + threadIdx.x) >> 5;
    int lane = threadIdx.x & 31;
    if (gw >= Bn) return;
    const float4* xr = (const float4*)(x + (size_t)gw * Dk);
    float s2 = 0.f, s1 = 0.f;
#pragma unroll
    for (int i = lane; i < Dk / 4; i += 32) {
        float4 v = xr[i];
        s1 += v.x + v.y + v.z + v.w;
        s2 = fmaf(v.x, v.x, s2); s2 = fmaf(v.y, v.y, s2);
        s2 = fmaf(v.z, v.z, s2); s2 = fmaf(v.w, v.w, s2);
        __nv_bfloat16 h[4] = {__float2bfloat16(v.x), __float2bfloat16(v.y),
                              __float2bfloat16(v.z), __float2bfloat16(v.w)};
        *(uint2*)&g_xhi[(size_t)gw * Dk + i * 4] = *(uint2*)h;
    }
#pragma unroll
    for (int o = 16; o; o >>= 1) {
        s1 += __shfl_down_sync(0xFFFFFFFFu, s1, o);
        s2 += __shfl_down_sync(0xFFFFFFFFu, s2, o);
    }
    if (lane == 0) g_rowconst[gw] = s2 + 2.0f * EPSF * s1 + (float)Dk * EPSF * EPSF;
}

__global__ void som_init_best() {
    int b = blockIdx.x * blockDim.x + threadIdx.x;
    if (b < Bn) { g_best[b] = ~0ull; g_best2[b] = ~0ull; }
    if (b == 0) g_ncand = 0;
}

// ---------------- pass 1: hi*hi GEMM + approx min + fp16 dot store ----------------
__global__ __launch_bounds__(256, 2) void som_mma(void) {
    extern __shared__ uint8_t dyn[];

    const int tid = threadIdx.x;
    const int lid = tid & 31;
    const int wid = tid >> 5;
    const int warp_m = wid >> 2;
    const int warp_n = wid & 3;
    const int bRow = blockIdx.x * BM;
    const int bCol = blockIdx.y * BN;

    float acc[4][4][4];
#pragma unroll
    for (int i = 0; i < 4; i++)
#pragma unroll
        for (int j = 0; j < 4; j++)
#pragma unroll
            for (int k = 0; k < 4; k++) acc[i][j][k] = 0.f;

    const uint32_t sb0 = smem_u32(dyn);

    // cp.async mapping: A 512x16B, B 512x16B per stage; 2 each per thread
    const int qa0 = tid, qa1 = tid + 256;
    const uint32_t a_s0 = (qa0 >> 2) * A_PITCH + (qa0 & 3) * 16;
    const uint32_t a_s1 = (qa1 >> 2) * A_PITCH + (qa1 & 3) * 16;
    const size_t a_g0 = (size_t)(bRow + (qa0 >> 2)) * Dk + (qa0 & 3) * 8;
    const size_t a_g1 = (size_t)(bRow + (qa1 >> 2)) * Dk + (qa1 & 3) * 8;
    const int qb0 = tid, qb1 = tid + 256;
    const uint32_t b_s0 = (qb0 >> 4) * B_PITCH + (qb0 & 15) * 16;
    const uint32_t b_s1 = (qb1 >> 4) * B_PITCH + (qb1 & 15) * 16;
    const size_t b_g0 = (size_t)(qb0 >> 4) * Mn + bCol + (qb0 & 15) * 8;
    const size_t b_g1 = (size_t)(qb1 >> 4) * Mn + bCol + (qb1 & 15) * 8;

    auto issue_stage = [&](int c) {
        const uint32_t sb = sb0 + (c & 1) * STAGE_SZ;
        const int k0 = c * BK;
        cp16(sb + A_HI + a_s0, g_xhi + a_g0 + k0);
        cp16(sb + A_HI + a_s1, g_xhi + a_g1 + k0);
        cp16(sb + B_HI + b_s0, g_whi + b_g0 + (size_t)k0 * Mn);
        cp16(sb + B_HI + b_s1, g_whi + b_g1 + (size_t)k0 * Mn);
    };

    const uint32_t a_ld = (warp_m * 64 + (lid & 15)) * A_PITCH + (lid >> 4) * 16;
    const uint32_t b_ld = (((lid >> 3) & 1) * 8 + (lid & 7)) * B_PITCH +
                          warp_n * 64 + ((lid >> 3) >> 1) * 16;

    issue_stage(0); cp_commit();
    issue_stage(1); cp_commit();

#pragma unroll 1
    for (int c = 0; c < NCH; c++) {
        cp_wait1();
        __syncthreads();
        const uint32_t sb = sb0 + (c & 1) * STAGE_SZ;

#pragma unroll
        for (int ks = 0; ks < 2; ks++) {
            uint32_t bh[2][4], af[4][4];
#pragma unroll
            for (int g = 0; g < 2; g++)
                ldsm_x4_t(bh[g], sb + B_HI + b_ld + ks * 16 * B_PITCH + g * 32);
#pragma unroll
            for (int mt = 0; mt < 4; mt++)
                ldsm_x4(af[mt], sb + A_HI + a_ld + mt * 16 * A_PITCH + ks * 32);
#pragma unroll
            for (int mt = 0; mt < 4; mt++)
#pragma unroll
                for (int nt = 0; nt < 4; nt++)
                    mma_bf16(acc[mt][nt], af[mt], &bh[nt >> 1][(nt & 1) * 2]);
        }

        __syncthreads();
        if (c + 2 < NCH) issue_stage(c + 2);
        cp_commit();
    }

    // ---- epilogue ----
    float ccv[4][2];
    const int cbase = bCol + warp_n * 32 + (lid & 3) * 2;
#pragma unroll
    for (int nt = 0; nt < 4; nt++) {
        ccv[nt][0] = __ldg(&g_colconst[cbase + nt * 8]);
        ccv[nt][1] = __ldg(&g_colconst[cbase + nt * 8 + 1]);
    }

    __syncthreads();   // stage buffers dead; reuse as fp16 dot tile [128][DOT_PITCH]
    __half* sdot = (__half*)dyn;

#pragma unroll
    for (int mt = 0; mt < 4; mt++) {
#pragma unroll
        for (int half = 0; half < 2; half++) {
            const int rloc = warp_m * 64 + mt * 16 + (lid >> 2) + half * 8;
            const int row = bRow + rloc;
            const float rc = __ldg(&g_rowconst[row]);
            unsigned long long best = ~0ull;
#pragma unroll
            for (int nt = 0; nt < 4; nt++) {
                __half2 hp;
#pragma unroll
                for (int q = 0; q < 2; q++) {
                    float dotf = acc[mt][nt][half * 2 + q];
                    __half dh = __float2half(dotf);
                    ((__half*)&hp)[q] = dh;
                    float sq = fmaxf(rc + ccv[nt][q] - 2.0f * __half2float(dh), 0.0f);
                    int m = cbase + nt * 8 + q;
                    unsigned long long key =
                        ((unsigned long long)__float_as_uint(sq) << 32) | (unsigned int)m;
                    best = (key < best) ? key : best;
                }
                // stash fp16 pair in smem tile
                *(__half2*)&sdot[rloc * DOT_PITCH + warp_n * 32 + nt * 8 + (lid & 3) * 2] = hp;
            }
            unsigned long long o1 = __shfl_xor_sync(0xFFFFFFFFu, best, 1);
            best = (o1 < best) ? o1 : best;
            unsigned long long o2 = __shfl_xor_sync(0xFFFFFFFFu, best, 2);
            best = (o2 < best) ? o2 : best;
            if ((lid & 3) == 0) atomicMin(&g_best[row], best);
        }
    }

    __syncthreads();
    // coalesced store of the 128x128 fp16 tile to g_dot
#pragma unroll
    for (int i = 0; i < 8; i++) {
        int chunk = tid + i * 256;        // 0..2047
        int r = chunk >> 4;               // row 0..127
        int o = (chunk & 15) * 8;         // half offset within row
        uint4 v = *(uint4*)&sdot[r * DOT_PITCH + o];
        *(uint4*)&g_dot[(size_t)(bRow + r) * Mn + bCol + o] = v;
    }
}

// ---------------- pass 2: candidate scan ----------------
__global__ void som_scan(void) {
    int m = blockIdx.x * blockDim.x + threadIdx.x;
    int b = blockIdx.y;
    float best_sq = __uint_as_float((unsigned int)(g_best[b] >> 32));
    float rc = g_rowconst[b];
    float sq = fmaxf(rc + g_colconst[m] -
                     2.0f * __half2float(g_dot[(size_t)b * Mn + m]), 0.0f);
    if (sq < best_sq + E_MARGIN) {
        int idx = atomicAdd(&g_ncand, 1);
        if (idx < CAND_CAP) g_cand[idx] = make_int2(b, m);
    }
}

// ---------------- pass 3: exact fp32 rescore of candidates ----------------
__global__ void som_rescore(const float* __restrict__ x, const float* __restrict__ w) {
    int gwarp = (blockIdx.x * blockDim.x + threadIdx.x) >> 5;
    int lane = threadIdx.x & 31;
    int nwarps = (gridDim.x * blockDim.x) >> 5;
    int n = g_ncand;
    if (n > CAND_CAP) n = CAND_CAP;
    for (int i = gwarp; i < n; i += nwarps) {
        int b = g_cand[i].x, m = g_cand[i].y;
        const float* xr = x + (size_t)b * Dk;
        float dot = 0.f;
#pragma unroll 4
        for (int k = lane; k < Dk; k += 32)
            dot = fmaf(xr[k], __ldg(&w[(size_t)k * Mn + m]), dot);
#pragma unroll
        for (int o = 16; o; o >>= 1) dot += __shfl_down_sync(0xFFFFFFFFu, dot, o);
        if (lane == 0) {
            float sq = fmaxf(g_rowconst[b] + g_colconst[m] - 2.0f * dot, 0.0f);
            unsigned long long key =
                ((unsigned long long)__float_as_uint(sq) << 32) | (unsigned int)m;
            atomicMin(&g_best2[b], key);
        }
    }
}

// ---------------- finalize ----------------
__global__ void som_finalize(const float* __restrict__ loc, float* __restrict__ out) {
    __shared__ float ssum[256];
    int tid = threadIdx.x;
    float local = 0.f;
    for (int b = tid; b < Bn; b += 256) {
        unsigned long long v = g_best2[b];
        unsigned int m = (unsigned int)(v & 0xFFFFFFFFu);
        float sq = __uint_as_float((unsigned int)(v >> 32));
        out[b] = (float)m;
        out[Bn + 2 * b + 0] = loc[2 * m + 0];
        out[Bn + 2 * b + 1] = loc[2 * m + 1];
        local += sqrtf(sq);
    }
    ssum[tid] = local;
    __syncthreads();
    for (int s = 128; s; s >>= 1) {
        if (tid < s) ssum[tid] += ssum[tid + s];
        __syncthreads();
    }
    if (tid == 0) out[3 * Bn] = ssum[0] / (float)Bn;
}

// ---------------- launch ----------------
extern "C" void kernel_launch(void* const* d_in, const int* in_sizes, int n_in,
                              void* d_out, int out_size) {
    const float* x = (const float*)d_in[0];   // [B, D]
    const float* w = (const float*)d_in[1];   // [D, M]
    const float* loc = (const float*)d_in[2]; // [M, 2]
    float* out = (float*)d_out;

    static int configured = 0;
    if (!configured) {
        cudaFuncSetAttribute(som_mma, cudaFuncAttributeMaxDynamicSharedMemorySize, DYN_BYTES);
        configured = 1;
    }

    som_wconv<<<dim3(Mn / 256, DSLICE), 256>>>(w);
    som_xconv<<<Bn * 32 / 256, 256>>>(x);
    som_colreduce<<<Mn / 256, 256>>>();
    som_init_best<<<Bn / 256, 256>>>();

    dim3 grid(Bn / BM, Mn / BN);   // x fastest: consecutive CTAs share the w panel (L2 reuse)
    som_mma<<<grid, 256, DYN_BYTES>>>();

    som_scan<<<dim3(Mn / 256, Bn), 256>>>();
    som_rescore<<<256, 256>>>(x, w);

    som_finalize<<<1, 256>>>(loc, out);
}

// round 8
// speedup vs baseline: 4.5401x; 1.2813x over previous
#include <cuda_runtime.h>
#include <cuda_bf16.h>
#include <cuda_fp16.h>
#include <cstdint>

#define Bn 2048
#define Dk 1024
#define Mn 16384
#define EPSF 1e-6f

#define BM 128
#define BN 128
#define BK 64
#define NCH (Dk / BK)        // 16 chunks

// padded pitches (bytes): A row = 64 bf16 = 128B -> 144; B row = 128 bf16 = 256B -> 272
#define A_PITCH 144
#define B_PITCH 272
#define A_HI 0
#define B_HI 18432           // 128*144
#define STAGE_SZ 35840       // + 64*272
#define NSTAGE 3
#define DOT_PITCH 136        // halves per smem dot row (272B, 16B-aligned)
#define DYN_BYTES (NSTAGE * STAGE_SZ)   // 107520 >= 128*136*2

#define DSLICE 8
#define E_MARGIN 3.5f
#define CAND_CAP (1 << 20)

// ---------------- device scratch ----------------
__device__ float g_rowconst[Bn];
__device__ float g_colconst[Mn];
__device__ float g_colpart[DSLICE * Mn];
__device__ unsigned long long g_best[Bn];    // approx (pass 1)
__device__ unsigned long long g_best2[Bn];   // exact (pass 3)
__device__ __nv_bfloat16 g_xhi[Bn * Dk];
__device__ __nv_bfloat16 g_whi[(size_t)Dk * Mn];
__device__ __half g_dot[(size_t)Bn * Mn];
__device__ int2 g_cand[CAND_CAP];
__device__ int g_ncand;

// ---------------- helpers ----------------
__device__ __forceinline__ uint32_t smem_u32(const void* p) {
    uint32_t a;
    asm("{ .reg .u64 t; cvta.to.shared.u64 t, %1; cvt.u32.u64 %0, t; }" : "=r"(a) : "l"(p));
    return a;
}
__device__ __forceinline__ void cp16(uint32_t s, const void* g) {
    asm volatile("cp.async.cg.shared.global [%0], [%1], 16;" :: "r"(s), "l"(g) : "memory");
}
__device__ __forceinline__ void cp_commit() { asm volatile("cp.async.commit_group;" ::: "memory"); }
__device__ __forceinline__ void cp_wait1()  { asm volatile("cp.async.wait_group 1;" ::: "memory"); }

__device__ __forceinline__ void ldsm_x4(uint32_t* r, uint32_t addr) {
    asm volatile("ldmatrix.sync.aligned.m8n8.x4.shared.b16 {%0,%1,%2,%3}, [%4];"
                 : "=r"(r[0]), "=r"(r[1]), "=r"(r[2]), "=r"(r[3]) : "r"(addr));
}
__device__ __forceinline__ void ldsm_x4_t(uint32_t* r, uint32_t addr) {
    asm volatile("ldmatrix.sync.aligned.m8n8.x4.trans.shared.b16 {%0,%1,%2,%3}, [%4];"
                 : "=r"(r[0]), "=r"(r[1]), "=r"(r[2]), "=r"(r[3]) : "r"(addr));
}
__device__ __forceinline__ void mma_bf16(float* c, const uint32_t* a, const uint32_t* b) {
    asm volatile(
        "mma.sync.aligned.m16n8k16.row.col.f32.bf16.bf16.f32 "
        "{%0,%1,%2,%3}, {%4,%5,%6,%7}, {%8,%9}, {%0,%1,%2,%3};"
        : "+f"(c[0]), "+f"(c[1]), "+f"(c[2]), "+f"(c[3])
        : "r"(a[0]), "r"(a[1]), "r"(a[2]), "r"(a[3]), "r"(b[0]), "r"(b[1]));
}

// ---------------- w convert + partial stats ----------------
__global__ void som_wconv(const float* __restrict__ w) {
    int m = blockIdx.x * blockDim.x + threadIdx.x;
    int z = blockIdx.y;
    int d0 = z * (Dk / DSLICE);
    float s2 = 0.f, s1 = 0.f;
#pragma unroll 4
    for (int i = 0; i < Dk / DSLICE; i++) {
        size_t idx = (size_t)(d0 + i) * Mn + m;
        float v = w[idx];
        s2 = fmaf(v, v, s2);
        s1 += v;
        g_whi[idx] = __float2bfloat16(v);
    }
    g_colpart[z * Mn + m] = s2 - 2.0f * EPSF * s1;
}

// colconst reduce + init best keys + candidate counter (merged)
__global__ void som_colreduce() {
    int m = blockIdx.x * blockDim.x + threadIdx.x;
    float s = 0.f;
#pragma unroll
    for (int z = 0; z < DSLICE; z++) s += g_colpart[z * Mn + m];
    g_colconst[m] = s;
    if (m < Bn) { g_best[m] = ~0ull; g_best2[m] = ~0ull; }
    if (m == 0) g_ncand = 0;
}

// ---------------- x convert + stats ----------------
__global__ void som_xconv(const float* __restrict__ x) {
    int gw = (blockIdx.x * blockDim.x + threadIdx.x) >> 5;
    int lane = threadIdx.x & 31;
    if (gw >= Bn) return;
    const float4* xr = (const float4*)(x + (size_t)gw * Dk);
    float s2 = 0.f, s1 = 0.f;
#pragma unroll
    for (int i = lane; i < Dk / 4; i += 32) {
        float4 v = xr[i];
        s1 += v.x + v.y + v.z + v.w;
        s2 = fmaf(v.x, v.x, s2); s2 = fmaf(v.y, v.y, s2);
        s2 = fmaf(v.z, v.z, s2); s2 = fmaf(v.w, v.w, s2);
        __nv_bfloat16 h[4] = {__float2bfloat16(v.x), __float2bfloat16(v.y),
                              __float2bfloat16(v.z), __float2bfloat16(v.w)};
        *(uint2*)&g_xhi[(size_t)gw * Dk + i * 4] = *(uint2*)h;
    }
#pragma unroll
    for (int o = 16; o; o >>= 1) {
        s1 += __shfl_down_sync(0xFFFFFFFFu, s1, o);
        s2 += __shfl_down_sync(0xFFFFFFFFu, s2, o);
    }
    if (lane == 0) g_rowconst[gw] = s2 + 2.0f * EPSF * s1 + (float)Dk * EPSF * EPSF;
}

// ---------------- pass 1: hi*hi GEMM + approx min + fp16 dot store ----------------
__global__ __launch_bounds__(256, 2) void som_mma(void) {
    extern __shared__ uint8_t dyn[];

    const int tid = threadIdx.x;
    const int lid = tid & 31;
    const int wid = tid >> 5;
    const int warp_m = wid >> 2;
    const int warp_n = wid & 3;
    const int bRow = blockIdx.x * BM;
    const int bCol = blockIdx.y * BN;

    float acc[4][4][4];
#pragma unroll
    for (int i = 0; i < 4; i++)
#pragma unroll
        for (int j = 0; j < 4; j++)
#pragma unroll
            for (int k = 0; k < 4; k++) acc[i][j][k] = 0.f;

    const uint32_t sb0 = smem_u32(dyn);

    // cp.async mapping, 4 x 16B each for A and B per stage per thread
    uint32_t a_soff[4], b_soff[4];
    size_t a_goff[4], b_goff[4];
#pragma unroll
    for (int i = 0; i < 4; i++) {
        int q = tid + i * 256;                 // 0..1023
        int ar = q >> 3, ak = q & 7;           // A: 128 rows x 8 chunks
        a_soff[i] = ar * A_PITCH + ak * 16;
        a_goff[i] = (size_t)(bRow + ar) * Dk + ak * 8;
        int br = q >> 4, bn = q & 15;          // B: 64 rows x 16 chunks
        b_soff[i] = br * B_PITCH + bn * 16;
        b_goff[i] = (size_t)br * Mn + bCol + bn * 8;
    }

    auto issue_stage = [&](int c) {
        const uint32_t sb = sb0 + (c % NSTAGE) * STAGE_SZ;
        const int k0 = c * BK;
#pragma unroll
        for (int i = 0; i < 4; i++) {
            cp16(sb + A_HI + a_soff[i], g_xhi + a_goff[i] + k0);
            cp16(sb + B_HI + b_soff[i], g_whi + b_goff[i] + (size_t)k0 * Mn);
        }
    };

    const uint32_t a_ld = (warp_m * 64 + (lid & 15)) * A_PITCH + (lid >> 4) * 16;
    const uint32_t b_ld = (((lid >> 3) & 1) * 8 + (lid & 7)) * B_PITCH +
                          warp_n * 64 + ((lid >> 3) >> 1) * 16;

    issue_stage(0); cp_commit();
    issue_stage(1); cp_commit();

#pragma unroll 1
    for (int c = 0; c < NCH; c++) {
        cp_wait1();
        __syncthreads();
        const uint32_t sb = sb0 + (c % NSTAGE) * STAGE_SZ;

#pragma unroll
        for (int ks = 0; ks < 4; ks++) {
            uint32_t bh[2][4], af[4][4];
#pragma unroll
            for (int g = 0; g < 2; g++)
                ldsm_x4_t(bh[g], sb + B_HI + b_ld + ks * 16 * B_PITCH + g * 32);
#pragma unroll
            for (int mt = 0; mt < 4; mt++)
                ldsm_x4(af[mt], sb + A_HI + a_ld + mt * 16 * A_PITCH + ks * 32);
#pragma unroll
            for (int mt = 0; mt < 4; mt++)
#pragma unroll
                for (int nt = 0; nt < 4; nt++)
                    mma_bf16(acc[mt][nt], af[mt], &bh[nt >> 1][(nt & 1) * 2]);
        }

        if (c + 2 < NCH) issue_stage(c + 2);
        cp_commit();
    }

    // ---- epilogue ----
    float ccv[4][2];
    const int cbase = bCol + warp_n * 32 + (lid & 3) * 2;
#pragma unroll
    for (int nt = 0; nt < 4; nt++) {
        ccv[nt][0] = __ldg(&g_colconst[cbase + nt * 8]);
        ccv[nt][1] = __ldg(&g_colconst[cbase + nt * 8 + 1]);
    }

    __syncthreads();   // stage buffers dead; reuse as fp16 dot tile [128][DOT_PITCH]
    __half* sdot = (__half*)dyn;

#pragma unroll
    for (int mt = 0; mt < 4; mt++) {
#pragma unroll
        for (int half = 0; half < 2; half++) {
            const int rloc = warp_m * 64 + mt * 16 + (lid >> 2) + half * 8;
            const int row = bRow + rloc;
            const float rc = __ldg(&g_rowconst[row]);
            unsigned long long best = ~0ull;
#pragma unroll
            for (int nt = 0; nt < 4; nt++) {
                __half2 hp;
#pragma unroll
                for (int q = 0; q < 2; q++) {
                    float dotf = acc[mt][nt][half * 2 + q];
                    __half dh = __float2half(dotf);
                    ((__half*)&hp)[q] = dh;
                    float sq = fmaxf(rc + ccv[nt][q] - 2.0f * __half2float(dh), 0.0f);
                    int m = cbase + nt * 8 + q;
                    unsigned long long key =
                        ((unsigned long long)__float_as_uint(sq) << 32) | (unsigned int)m;
                    best = (key < best) ? key : best;
                }
                *(__half2*)&sdot[rloc * DOT_PITCH + warp_n * 32 + nt * 8 + (lid & 3) * 2] = hp;
            }
            unsigned long long o1 = __shfl_xor_sync(0xFFFFFFFFu, best, 1);
            best = (o1 < best) ? o1 : best;
            unsigned long long o2 = __shfl_xor_sync(0xFFFFFFFFu, best, 2);
            best = (o2 < best) ? o2 : best;
            if ((lid & 3) == 0) atomicMin(&g_best[row], best);
        }
    }

    __syncthreads();
    // coalesced store of the 128x128 fp16 tile to g_dot
#pragma unroll
    for (int i = 0; i < 8; i++) {
        int chunk = tid + i * 256;        // 0..2047
        int r = chunk >> 4;
        int o = (chunk & 15) * 8;
        uint4 v = *(uint4*)&sdot[r * DOT_PITCH + o];
        *(uint4*)&g_dot[(size_t)(bRow + r) * Mn + bCol + o] = v;
    }
}

// ---------------- pass 2: candidate scan (8 halves / thread) ----------------
__global__ void som_scan(void) {
    int t = blockIdx.x * blockDim.x + threadIdx.x;   // 0 .. Mn/8-1
    int b = blockIdx.y;
    int m0 = t * 8;
    float thresh = __uint_as_float((unsigned int)(g_best[b] >> 32)) + E_MARGIN;
    float rc = g_rowconst[b];
    uint4 dv = *(const uint4*)&g_dot[(size_t)b * Mn + m0];
    const __half2* dh = (const __half2*)&dv;
#pragma unroll
    for (int i = 0; i < 4; i++) {
        float2 d = __half22float2(dh[i]);
        float sq0 = fmaxf(rc + __ldg(&g_colconst[m0 + 2 * i])     - 2.0f * d.x, 0.0f);
        float sq1 = fmaxf(rc + __ldg(&g_colconst[m0 + 2 * i + 1]) - 2.0f * d.y, 0.0f);
        if (sq0 < thresh) {
            int idx = atomicAdd(&g_ncand, 1);
            if (idx < CAND_CAP) g_cand[idx] = make_int2(b, m0 + 2 * i);
        }
        if (sq1 < thresh) {
            int idx = atomicAdd(&g_ncand, 1);
            if (idx < CAND_CAP) g_cand[idx] = make_int2(b, m0 + 2 * i + 1);
        }
    }
}

// ---------------- pass 3: exact fp32 rescore ----------------
__global__ void som_rescore(const float* __restrict__ x, const float* __restrict__ w) {
    int gwarp = (blockIdx.x * blockDim.x + threadIdx.x) >> 5;
    int lane = threadIdx.x & 31;
    int nwarps = (gridDim.x * blockDim.x) >> 5;
    int n = g_ncand;
    if (n > CAND_CAP) n = CAND_CAP;
    for (int i = gwarp; i < n; i += nwarps) {
        int b = g_cand[i].x, m = g_cand[i].y;
        const float* xr = x + (size_t)b * Dk;
        float dot = 0.f;
#pragma unroll 4
        for (int k = lane; k < Dk; k += 32)
            dot = fmaf(xr[k], __ldg(&w[(size_t)k * Mn + m]), dot);
#pragma unroll
        for (int o = 16; o; o >>= 1) dot += __shfl_down_sync(0xFFFFFFFFu, dot, o);
        if (lane == 0) {
            float sq = fmaxf(g_rowconst[b] + g_colconst[m] - 2.0f * dot, 0.0f);
            unsigned long long key =
                ((unsigned long long)__float_as_uint(sq) << 32) | (unsigned int)m;
            atomicMin(&g_best2[b], key);
        }
    }
}

// ---------------- finalize ----------------
__global__ void som_finalize(const float* __restrict__ loc, float* __restrict__ out) {
    __shared__ float ssum[256];
    int tid = threadIdx.x;
    float local = 0.f;
    for (int b = tid; b < Bn; b += 256) {
        unsigned long long v = g_best2[b];
        unsigned int m = (unsigned int)(v & 0xFFFFFFFFu);
        float sq = __uint_as_float((unsigned int)(v >> 32));
        out[b] = (float)m;
        out[Bn + 2 * b + 0] = loc[2 * m + 0];
        out[Bn + 2 * b + 1] = loc[2 * m + 1];
        local += sqrtf(sq);
    }
    ssum[tid] = local;
    __syncthreads();
    for (int s = 128; s; s >>= 1) {
        if (tid < s) ssum[tid] += ssum[tid + s];
        __syncthreads();
    }
    if (tid == 0) out[3 * Bn] = ssum[0] / (float)Bn;
}

// ---------------- launch ----------------
extern "C" void kernel_launch(void* const* d_in, const int* in_sizes, int n_in,
                              void* d_out, int out_size) {
    const float* x = (const float*)d_in[0];   // [B, D]
    const float* w = (const float*)d_in[1];   // [D, M]
    const float* loc = (const float*)d_in[2]; // [M, 2]
    float* out = (float*)d_out;

    static int configured = 0;
    if (!configured) {
        cudaFuncSetAttribute(som_mma, cudaFuncAttributeMaxDynamicSharedMemorySize, DYN_BYTES);
        configured = 1;
    }

    som_wconv<<<dim3(Mn / 256, DSLICE), 256>>>(w);
    som_xconv<<<Bn * 32 / 256, 256>>>(x);
    som_colreduce<<<Mn / 256, 256>>>();

    dim3 grid(Bn / BM, Mn / BN);   // x fastest: consecutive CTAs share the w panel (L2 reuse)
    som_mma<<<grid, 256, DYN_BYTES>>>();

    som_scan<<<dim3(Mn / 8 / 256, Bn), 256>>>();
    som_rescore<<<256, 256>>>(x, w);

    som_finalize<<<1, 256>>>(loc, out);
}